// round 11
// baseline (speedup 1.0000x reference)
#include <cuda_runtime.h>

// ============================================================================
// GCNEncoder: 3-layer GCN on GB300.
//   per layer: out[d] = dinv[d] * ( G[d] + sum_{e: dst=d} G[src_e] ) + b
//   where G = (act(in) @ W) * dinv[row],  dinv = rsqrt(1 + indeg)
// Pipeline: build CSR by dst (counting sort) once, then per layer:
//   GEMM (W in smem, 8 rows/warp, dinv folded into epilogue, relu folded
//   into input read) -> node-parallel gather-aggregate (no atomics on
//   feature data).
// ============================================================================

#define FULLMASK 0xffffffffu

static constexpr int MAXN = 100000;
static constexpr int MAXE = 1600000;

__device__ int   g_deg[MAXN];
__device__ float g_dinv[MAXN];
__device__ int   g_rowptr[MAXN + 1];
__device__ int   g_cursor[MAXN];
__device__ int   g_csr[MAXE];
__device__ int   g_bsum[1024];
__device__ int   g_boff[1024];
__device__ float g_G[(size_t)MAXN * 128];
__device__ float g_H[(size_t)MAXN * 128];

// ---------------------------------------------------------------------------
// CSR build
// ---------------------------------------------------------------------------

__global__ void count_deg_kernel(const int* __restrict__ dst, int e) {
    int i = blockIdx.x * blockDim.x + threadIdx.x;
    if (i < e) atomicAdd(&g_deg[dst[i]], 1);
}

// Hillis-Steele block scan over 1024 elements; also emits dinv.
__global__ void scan1_kernel(int n) {
    __shared__ int s[1024];
    int tid = threadIdx.x;
    int i = blockIdx.x * 1024 + tid;
    int v = (i < n) ? g_deg[i] : 0;
    if (i < n) g_dinv[i] = rsqrtf((float)v + 1.0f);
    s[tid] = v;
    __syncthreads();
    for (int off = 1; off < 1024; off <<= 1) {
        int t = (tid >= off) ? s[tid - off] : 0;
        __syncthreads();
        s[tid] += t;
        __syncthreads();
    }
    if (i < n) g_rowptr[i] = s[tid] - v;   // exclusive within block
    if (tid == 1023) g_bsum[blockIdx.x] = s[1023];
}

__global__ void scan2_kernel(int nb) {
    __shared__ int s[1024];
    int tid = threadIdx.x;
    int v = (tid < nb) ? g_bsum[tid] : 0;
    s[tid] = v;
    __syncthreads();
    for (int off = 1; off < 1024; off <<= 1) {
        int t = (tid >= off) ? s[tid - off] : 0;
        __syncthreads();
        s[tid] += t;
        __syncthreads();
    }
    g_boff[tid] = s[tid] - v;   // exclusive block offsets
}

__global__ void scan3_kernel(int n, int e) {
    int tid = threadIdx.x;
    int i = blockIdx.x * 1024 + tid;
    if (i < n) {
        int r = g_rowptr[i] + g_boff[blockIdx.x];
        g_rowptr[i] = r;
        g_cursor[i] = r;
    }
    if (i == 0) g_rowptr[n] = e;
}

__global__ void scatter_kernel(const int* __restrict__ src,
                               const int* __restrict__ dst, int e) {
    int i = blockIdx.x * blockDim.x + threadIdx.x;
    if (i < e) {
        int d = dst[i];
        int pos = atomicAdd(&g_cursor[d], 1);
        g_csr[pos] = src[i];
    }
}

// ---------------------------------------------------------------------------
// GEMM: G[row] = (act(X[row]) @ W) * dinv[row]
// W entirely in smem; 8 warps/block, 8 rows/warp register-blocked.
// ---------------------------------------------------------------------------

template <int IN, int OUT, bool RELU>
__global__ void __launch_bounds__(256)
gemm_kernel(const float* __restrict__ X, const float* __restrict__ W,
            float* __restrict__ G, int n) {
    constexpr int R  = 8;
    constexpr int VO = OUT / 32;
    extern __shared__ float sm[];
    float* Wsh = sm;              // IN*OUT
    float* xs  = sm + IN * OUT;   // 8 warps * R * IN

    int tid  = threadIdx.x;
    int lane = tid & 31;
    int w    = tid >> 5;

    // stage W
    for (int t = tid; t < (IN * OUT) / 4; t += 256)
        ((float4*)Wsh)[t] = ((const float4*)W)[t];

    int rowBase = blockIdx.x * 64 + w * R;
    float* xw = xs + w * (R * IN);

    // stage 8 input rows (relu applied on read)
#pragma unroll
    for (int r = 0; r < R; r++) {
        int row = rowBase + r;
        float4 v = make_float4(0.f, 0.f, 0.f, 0.f);
        if (row < n) {
            v = *(const float4*)(X + (size_t)row * IN + lane * 4);
            if (RELU) {
                v.x = fmaxf(v.x, 0.f); v.y = fmaxf(v.y, 0.f);
                v.z = fmaxf(v.z, 0.f); v.w = fmaxf(v.w, 0.f);
            }
        }
        *(float4*)(xw + r * IN + lane * 4) = v;
    }
    __syncthreads();

    float acc[R][VO];
#pragma unroll
    for (int r = 0; r < R; r++)
#pragma unroll
        for (int j = 0; j < VO; j++) acc[r][j] = 0.f;

#pragma unroll 2
    for (int k0 = 0; k0 < IN; k0 += 4) {
        float4 xv[R];
#pragma unroll
        for (int r = 0; r < R; r++)
            xv[r] = *(const float4*)(xw + r * IN + k0);
#pragma unroll
        for (int kk = 0; kk < 4; kk++) {
            int k = k0 + kk;
            if constexpr (VO == 4) {
                float4 wv = *(const float4*)(Wsh + k * OUT + lane * 4);
#pragma unroll
                for (int r = 0; r < R; r++) {
                    float xk = ((const float*)&xv[r])[kk];
                    acc[r][0] = fmaf(xk, wv.x, acc[r][0]);
                    acc[r][1] = fmaf(xk, wv.y, acc[r][1]);
                    acc[r][2] = fmaf(xk, wv.z, acc[r][2]);
                    acc[r][3] = fmaf(xk, wv.w, acc[r][3]);
                }
            } else {
                float2 wv = *(const float2*)(Wsh + k * OUT + lane * 2);
#pragma unroll
                for (int r = 0; r < R; r++) {
                    float xk = ((const float*)&xv[r])[kk];
                    acc[r][0] = fmaf(xk, wv.x, acc[r][0]);
                    acc[r][1] = fmaf(xk, wv.y, acc[r][1]);
                }
            }
        }
    }

#pragma unroll
    for (int r = 0; r < R; r++) {
        int row = rowBase + r;
        if (row < n) {
            float dv = g_dinv[row];
            if constexpr (VO == 4) {
                float4 o = make_float4(acc[r][0] * dv, acc[r][1] * dv,
                                       acc[r][2] * dv, acc[r][3] * dv);
                *(float4*)(G + (size_t)row * OUT + lane * 4) = o;
            } else {
                float2 o = make_float2(acc[r][0] * dv, acc[r][1] * dv);
                *(float2*)(G + (size_t)row * OUT + lane * 2) = o;
            }
        }
    }
}

// ---------------------------------------------------------------------------
// Aggregate: out[d] = dinv[d] * (G[d] + sum_{src in N(d)} G[src]) + bias
// One warp per dst node; neighbor indices loaded cooperatively (coalesced),
// broadcast via shuffle; 8 gathers in flight per inner group (MLP ~32 per
// warp) to cover L2-hit latency (~250 cyc). rowptr fetched by 2 lanes and
// broadcast (avoids 32x-redundant scalar LDG).
// ---------------------------------------------------------------------------

template <int OUT>
__global__ void __launch_bounds__(256)
agg_kernel(const float* __restrict__ G, const float* __restrict__ bias,
           float* __restrict__ out, int n) {
    constexpr int VO = OUT / 32;
    int gwarp = (blockIdx.x * blockDim.x + threadIdx.x) >> 5;
    int lane  = threadIdx.x & 31;
    if (gwarp >= n) return;
    int d = gwarp;

    // lanes 0,1 load rowptr[d], rowptr[d+1]; broadcast to warp
    int rp = 0;
    if (lane < 2) rp = g_rowptr[d + lane];
    int start = __shfl_sync(FULLMASK, rp, 0);
    int end   = __shfl_sync(FULLMASK, rp, 1);

    float accA[VO], accB[VO];
    // self term
    if constexpr (VO == 4) {
        float4 v = *(const float4*)(G + (size_t)d * OUT + lane * 4);
        accA[0] = v.x; accA[1] = v.y; accA[2] = v.z; accA[3] = v.w;
    } else {
        float2 v = *(const float2*)(G + (size_t)d * OUT + lane * 2);
        accA[0] = v.x; accA[1] = v.y;
    }
#pragma unroll
    for (int j = 0; j < VO; j++) accB[j] = 0.f;

    for (int base = start; base < end; base += 32) {
        int idx = base + lane;
        int my  = (idx < end) ? g_csr[idx] : 0;
        int cnt = min(32, end - base);
        int j = 0;
        for (; j + 8 <= cnt; j += 8) {
            int s0 = __shfl_sync(FULLMASK, my, j);
            int s1 = __shfl_sync(FULLMASK, my, j + 1);
            int s2 = __shfl_sync(FULLMASK, my, j + 2);
            int s3 = __shfl_sync(FULLMASK, my, j + 3);
            int s4 = __shfl_sync(FULLMASK, my, j + 4);
            int s5 = __shfl_sync(FULLMASK, my, j + 5);
            int s6 = __shfl_sync(FULLMASK, my, j + 6);
            int s7 = __shfl_sync(FULLMASK, my, j + 7);
            if constexpr (VO == 4) {
                float4 v0 = *(const float4*)(G + (size_t)s0 * OUT + lane * 4);
                float4 v1 = *(const float4*)(G + (size_t)s1 * OUT + lane * 4);
                float4 v2 = *(const float4*)(G + (size_t)s2 * OUT + lane * 4);
                float4 v3 = *(const float4*)(G + (size_t)s3 * OUT + lane * 4);
                float4 v4 = *(const float4*)(G + (size_t)s4 * OUT + lane * 4);
                float4 v5 = *(const float4*)(G + (size_t)s5 * OUT + lane * 4);
                float4 v6 = *(const float4*)(G + (size_t)s6 * OUT + lane * 4);
                float4 v7 = *(const float4*)(G + (size_t)s7 * OUT + lane * 4);
                accA[0] += v0.x; accA[1] += v0.y; accA[2] += v0.z; accA[3] += v0.w;
                accB[0] += v1.x; accB[1] += v1.y; accB[2] += v1.z; accB[3] += v1.w;
                accA[0] += v2.x; accA[1] += v2.y; accA[2] += v2.z; accA[3] += v2.w;
                accB[0] += v3.x; accB[1] += v3.y; accB[2] += v3.z; accB[3] += v3.w;
                accA[0] += v4.x; accA[1] += v4.y; accA[2] += v4.z; accA[3] += v4.w;
                accB[0] += v5.x; accB[1] += v5.y; accB[2] += v5.z; accB[3] += v5.w;
                accA[0] += v6.x; accA[1] += v6.y; accA[2] += v6.z; accA[3] += v6.w;
                accB[0] += v7.x; accB[1] += v7.y; accB[2] += v7.z; accB[3] += v7.w;
            } else {
                float2 v0 = *(const float2*)(G + (size_t)s0 * OUT + lane * 2);
                float2 v1 = *(const float2*)(G + (size_t)s1 * OUT + lane * 2);
                float2 v2 = *(const float2*)(G + (size_t)s2 * OUT + lane * 2);
                float2 v3 = *(const float2*)(G + (size_t)s3 * OUT + lane * 2);
                float2 v4 = *(const float2*)(G + (size_t)s4 * OUT + lane * 2);
                float2 v5 = *(const float2*)(G + (size_t)s5 * OUT + lane * 2);
                float2 v6 = *(const float2*)(G + (size_t)s6 * OUT + lane * 2);
                float2 v7 = *(const float2*)(G + (size_t)s7 * OUT + lane * 2);
                accA[0] += v0.x; accA[1] += v0.y;
                accB[0] += v1.x; accB[1] += v1.y;
                accA[0] += v2.x; accA[1] += v2.y;
                accB[0] += v3.x; accB[1] += v3.y;
                accA[0] += v4.x; accA[1] += v4.y;
                accB[0] += v5.x; accB[1] += v5.y;
                accA[0] += v6.x; accA[1] += v6.y;
                accB[0] += v7.x; accB[1] += v7.y;
            }
        }
        for (; j < cnt; j++) {
            int s = __shfl_sync(FULLMASK, my, j);
            if constexpr (VO == 4) {
                float4 v = *(const float4*)(G + (size_t)s * OUT + lane * 4);
                accA[0] += v.x; accA[1] += v.y; accA[2] += v.z; accA[3] += v.w;
            } else {
                float2 v = *(const float2*)(G + (size_t)s * OUT + lane * 2);
                accA[0] += v.x; accA[1] += v.y;
            }
        }
    }

    float dv = g_dinv[d];
    if constexpr (VO == 4) {
        float4 bv = *(const float4*)(bias + lane * 4);
        float4 o = make_float4((accA[0] + accB[0]) * dv + bv.x,
                               (accA[1] + accB[1]) * dv + bv.y,
                               (accA[2] + accB[2]) * dv + bv.z,
                               (accA[3] + accB[3]) * dv + bv.w);
        *(float4*)(out + (size_t)d * OUT + lane * 4) = o;
    } else {
        float2 bv = *(const float2*)(bias + lane * 2);
        float2 o = make_float2((accA[0] + accB[0]) * dv + bv.x,
                               (accA[1] + accB[1]) * dv + bv.y);
        *(float2*)(out + (size_t)d * OUT + lane * 2) = o;
    }
}

// ---------------------------------------------------------------------------
// Launch
// ---------------------------------------------------------------------------

extern "C" void kernel_launch(void* const* d_in, const int* in_sizes, int n_in,
                              void* d_out, int out_size) {
    const float* x  = (const float*)d_in[0];
    const int*   ei = (const int*)d_in[1];
    const float* W1 = (const float*)d_in[2];
    const float* b1 = (const float*)d_in[3];
    const float* W2 = (const float*)d_in[4];
    const float* b2 = (const float*)d_in[5];
    const float* W3 = (const float*)d_in[6];
    const float* b3 = (const float*)d_in[7];

    int E  = in_sizes[1] / 2;
    int D1 = in_sizes[3];            // 128
    int D0 = in_sizes[2] / D1;       // 128
    int N  = in_sizes[0] / D0;       // 100000
    if (N > MAXN) N = MAXN;
    if (E > MAXE) E = MAXE;

    const int* src = ei;
    const int* dst = ei + E;

    float *G, *H;
    cudaGetSymbolAddress((void**)&G, g_G);
    cudaGetSymbolAddress((void**)&H, g_H);
    void* degPtr;
    cudaGetSymbolAddress(&degPtr, g_deg);

    // dynamic smem sizes for GEMM variants
    const int SM128 = (128 * 128 + 8 * 8 * 128) * (int)sizeof(float);  // 96 KB
    const int SM64  = (128 * 64  + 8 * 8 * 128) * (int)sizeof(float);  // 64 KB
    cudaFuncSetAttribute(gemm_kernel<128, 128, false>,
                         cudaFuncAttributeMaxDynamicSharedMemorySize, SM128);
    cudaFuncSetAttribute(gemm_kernel<128, 128, true>,
                         cudaFuncAttributeMaxDynamicSharedMemorySize, SM128);
    cudaFuncSetAttribute(gemm_kernel<128, 64, true>,
                         cudaFuncAttributeMaxDynamicSharedMemorySize, SM64);

    int nb1024 = (N + 1023) / 1024;
    int ebs    = (E + 255) / 256;
    int gemmBlocks = (N + 63) / 64;
    int aggBlocks  = (N + 7) / 8;   // 8 warps/block, warp per node

    // ---- CSR build ----
    cudaMemsetAsync(degPtr, 0, (size_t)N * sizeof(int));
    count_deg_kernel<<<ebs, 256>>>(dst, E);
    scan1_kernel<<<nb1024, 1024>>>(N);   // also computes dinv
    scan2_kernel<<<1, 1024>>>(nb1024);
    scan3_kernel<<<nb1024, 1024>>>(N, E);
    scatter_kernel<<<ebs, 256>>>(src, dst, E);

    // ---- layer 1 ----
    gemm_kernel<128, 128, false><<<gemmBlocks, 256, SM128>>>(x, W1, G, N);
    agg_kernel<128><<<aggBlocks, 256>>>(G, b1, H, N);
    // ---- layer 2 (relu folded into GEMM input read) ----
    gemm_kernel<128, 128, true><<<gemmBlocks, 256, SM128>>>(H, W2, G, N);
    agg_kernel<128><<<aggBlocks, 256>>>(G, b2, H, N);
    // ---- layer 3 ----
    gemm_kernel<128, 64, true><<<gemmBlocks, 256, SM64>>>(H, W3, G, N);
    agg_kernel<64><<<aggBlocks, 256>>>(G, b3, (float*)d_out, N);
}

// round 16
// speedup vs baseline: 1.1068x; 1.1068x over previous
#include <cuda_runtime.h>

// ============================================================================
// GCNEncoder: 3-layer GCN on GB300.
//   per layer: out[d] = dinv[d] * ( G[d] + sum_{e: dst=d} G[src_e] ) + b
//   where G = (act(in) @ W) * dinv[row],  dinv = rsqrt(1 + indeg)
// CSR counting-sort -> [per layer] GEMM (W in smem, 8 rows/warp, f32x2
// packed FMA) -> warp-per-node gather aggregate.
// R11 change: GEMM inner loop uses fma.rn.f32x2 (FFMA2) — ptxas never emits
// it from C++; doubles fp32 FMA throughput on sm_103a.
// ============================================================================

#define FULLMASK 0xffffffffu

typedef unsigned long long u64;

__device__ __forceinline__ u64 pack2(float lo, float hi) {
    u64 r; asm("mov.b64 %0, {%1, %2};" : "=l"(r) : "f"(lo), "f"(hi)); return r;
}
__device__ __forceinline__ void unpack2(u64 v, float& lo, float& hi) {
    asm("mov.b64 {%0, %1}, %2;" : "=f"(lo), "=f"(hi) : "l"(v));
}
__device__ __forceinline__ u64 ffma2(u64 a, u64 b, u64 c) {
    u64 d; asm("fma.rn.f32x2 %0, %1, %2, %3;" : "=l"(d) : "l"(a), "l"(b), "l"(c)); return d;
}

static constexpr int MAXN = 100000;
static constexpr int MAXE = 1600000;

__device__ int   g_deg[MAXN];
__device__ float g_dinv[MAXN];
__device__ int   g_rowptr[MAXN + 1];
__device__ int   g_cursor[MAXN];
__device__ int   g_csr[MAXE];
__device__ int   g_bsum[1024];
__device__ int   g_boff[1024];
__device__ float g_G[(size_t)MAXN * 128];
__device__ float g_H[(size_t)MAXN * 128];

// ---------------------------------------------------------------------------
// CSR build
// ---------------------------------------------------------------------------

__global__ void count_deg_kernel(const int* __restrict__ dst, int e) {
    int i = blockIdx.x * blockDim.x + threadIdx.x;
    if (i < e) atomicAdd(&g_deg[dst[i]], 1);
}

// Hillis-Steele block scan over 1024 elements; also emits dinv.
__global__ void scan1_kernel(int n) {
    __shared__ int s[1024];
    int tid = threadIdx.x;
    int i = blockIdx.x * 1024 + tid;
    int v = (i < n) ? g_deg[i] : 0;
    if (i < n) g_dinv[i] = rsqrtf((float)v + 1.0f);
    s[tid] = v;
    __syncthreads();
    for (int off = 1; off < 1024; off <<= 1) {
        int t = (tid >= off) ? s[tid - off] : 0;
        __syncthreads();
        s[tid] += t;
        __syncthreads();
    }
    if (i < n) g_rowptr[i] = s[tid] - v;   // exclusive within block
    if (tid == 1023) g_bsum[blockIdx.x] = s[1023];
}

__global__ void scan2_kernel(int nb) {
    __shared__ int s[1024];
    int tid = threadIdx.x;
    int v = (tid < nb) ? g_bsum[tid] : 0;
    s[tid] = v;
    __syncthreads();
    for (int off = 1; off < 1024; off <<= 1) {
        int t = (tid >= off) ? s[tid - off] : 0;
        __syncthreads();
        s[tid] += t;
        __syncthreads();
    }
    g_boff[tid] = s[tid] - v;   // exclusive block offsets
}

__global__ void scan3_kernel(int n, int e) {
    int tid = threadIdx.x;
    int i = blockIdx.x * 1024 + tid;
    if (i < n) {
        int r = g_rowptr[i] + g_boff[blockIdx.x];
        g_rowptr[i] = r;
        g_cursor[i] = r;
    }
    if (i == 0) g_rowptr[n] = e;
}

__global__ void scatter_kernel(const int* __restrict__ src,
                               const int* __restrict__ dst, int e) {
    int i = blockIdx.x * blockDim.x + threadIdx.x;
    if (i < e) {
        int d = dst[i];
        int pos = atomicAdd(&g_cursor[d], 1);
        g_csr[pos] = src[i];
    }
}

// ---------------------------------------------------------------------------
// GEMM: G[row] = (act(X[row]) @ W) * dinv[row]
// W entirely in smem; 8 warps/block, 8 rows/warp register-blocked.
// Inner loop: packed f32x2 FMA (FFMA2). B-operand pairs come straight from
// the smem LDS.128 (ulonglong2) with no packing; A broadcast value packed
// once per (r,k) on the ALU pipe.
// ---------------------------------------------------------------------------

template <int IN, int OUT, bool RELU>
__global__ void __launch_bounds__(256)
gemm_kernel(const float* __restrict__ X, const float* __restrict__ W,
            float* __restrict__ G, int n) {
    constexpr int R  = 8;
    constexpr int VO = OUT / 32;     // floats per lane (4 or 2)
    constexpr int VP = VO / 2;       // f32x2 pairs per lane (2 or 1)
    extern __shared__ float sm[];
    float* Wsh = sm;              // IN*OUT
    float* xs  = sm + IN * OUT;   // 8 warps * R * IN

    int tid  = threadIdx.x;
    int lane = tid & 31;
    int w    = tid >> 5;

    // stage W
    for (int t = tid; t < (IN * OUT) / 4; t += 256)
        ((float4*)Wsh)[t] = ((const float4*)W)[t];

    int rowBase = blockIdx.x * 64 + w * R;
    float* xw = xs + w * (R * IN);

    // stage 8 input rows (relu applied on read)
#pragma unroll
    for (int r = 0; r < R; r++) {
        int row = rowBase + r;
        float4 v = make_float4(0.f, 0.f, 0.f, 0.f);
        if (row < n) {
            v = *(const float4*)(X + (size_t)row * IN + lane * 4);
            if (RELU) {
                v.x = fmaxf(v.x, 0.f); v.y = fmaxf(v.y, 0.f);
                v.z = fmaxf(v.z, 0.f); v.w = fmaxf(v.w, 0.f);
            }
        }
        *(float4*)(xw + r * IN + lane * 4) = v;
    }
    __syncthreads();

    u64 acc2[R][VP];
#pragma unroll
    for (int r = 0; r < R; r++)
#pragma unroll
        for (int j = 0; j < VP; j++) acc2[r][j] = 0ull;  // {0.0f, 0.0f}

#pragma unroll 2
    for (int k0 = 0; k0 < IN; k0 += 4) {
        float4 xv[R];
#pragma unroll
        for (int r = 0; r < R; r++)
            xv[r] = *(const float4*)(xw + r * IN + k0);   // broadcast LDS
#pragma unroll
        for (int kk = 0; kk < 4; kk++) {
            int k = k0 + kk;
            if constexpr (VP == 2) {
                ulonglong2 b2 = *(const ulonglong2*)(Wsh + k * OUT + lane * 4);
#pragma unroll
                for (int r = 0; r < R; r++) {
                    float xk = ((const float*)&xv[r])[kk];
                    u64 a2 = pack2(xk, xk);
                    acc2[r][0] = ffma2(a2, b2.x, acc2[r][0]);
                    acc2[r][1] = ffma2(a2, b2.y, acc2[r][1]);
                }
            } else {
                u64 b = *(const u64*)(Wsh + k * OUT + lane * 2);
#pragma unroll
                for (int r = 0; r < R; r++) {
                    float xk = ((const float*)&xv[r])[kk];
                    u64 a2 = pack2(xk, xk);
                    acc2[r][0] = ffma2(a2, b, acc2[r][0]);
                }
            }
        }
    }

#pragma unroll
    for (int r = 0; r < R; r++) {
        int row = rowBase + r;
        if (row < n) {
            float dv = g_dinv[row];
            if constexpr (VP == 2) {
                float c0, c1, c2, c3;
                unpack2(acc2[r][0], c0, c1);
                unpack2(acc2[r][1], c2, c3);
                float4 o = make_float4(c0 * dv, c1 * dv, c2 * dv, c3 * dv);
                *(float4*)(G + (size_t)row * OUT + lane * 4) = o;
            } else {
                float c0, c1;
                unpack2(acc2[r][0], c0, c1);
                float2 o = make_float2(c0 * dv, c1 * dv);
                *(float2*)(G + (size_t)row * OUT + lane * 2) = o;
            }
        }
    }
}

// ---------------------------------------------------------------------------
// Aggregate: out[d] = dinv[d] * (G[d] + sum_{src in N(d)} G[src]) + bias
// One warp per dst node; neighbor indices loaded cooperatively (coalesced),
// broadcast via shuffle; 8 gathers in flight per inner group (MLP ~32 per
// warp) to cover L2-hit latency. rowptr fetched by 2 lanes and broadcast.
// ---------------------------------------------------------------------------

template <int OUT>
__global__ void __launch_bounds__(256)
agg_kernel(const float* __restrict__ G, const float* __restrict__ bias,
           float* __restrict__ out, int n) {
    constexpr int VO = OUT / 32;
    int gwarp = (blockIdx.x * blockDim.x + threadIdx.x) >> 5;
    int lane  = threadIdx.x & 31;
    if (gwarp >= n) return;
    int d = gwarp;

    // lanes 0,1 load rowptr[d], rowptr[d+1]; broadcast to warp
    int rp = 0;
    if (lane < 2) rp = g_rowptr[d + lane];
    int start = __shfl_sync(FULLMASK, rp, 0);
    int end   = __shfl_sync(FULLMASK, rp, 1);

    float accA[VO], accB[VO];
    // self term
    if constexpr (VO == 4) {
        float4 v = *(const float4*)(G + (size_t)d * OUT + lane * 4);
        accA[0] = v.x; accA[1] = v.y; accA[2] = v.z; accA[3] = v.w;
    } else {
        float2 v = *(const float2*)(G + (size_t)d * OUT + lane * 2);
        accA[0] = v.x; accA[1] = v.y;
    }
#pragma unroll
    for (int j = 0; j < VO; j++) accB[j] = 0.f;

    for (int base = start; base < end; base += 32) {
        int idx = base + lane;
        int my  = (idx < end) ? g_csr[idx] : 0;
        int cnt = min(32, end - base);
        int j = 0;
        for (; j + 8 <= cnt; j += 8) {
            int s0 = __shfl_sync(FULLMASK, my, j);
            int s1 = __shfl_sync(FULLMASK, my, j + 1);
            int s2 = __shfl_sync(FULLMASK, my, j + 2);
            int s3 = __shfl_sync(FULLMASK, my, j + 3);
            int s4 = __shfl_sync(FULLMASK, my, j + 4);
            int s5 = __shfl_sync(FULLMASK, my, j + 5);
            int s6 = __shfl_sync(FULLMASK, my, j + 6);
            int s7 = __shfl_sync(FULLMASK, my, j + 7);
            if constexpr (VO == 4) {
                float4 v0 = *(const float4*)(G + (size_t)s0 * OUT + lane * 4);
                float4 v1 = *(const float4*)(G + (size_t)s1 * OUT + lane * 4);
                float4 v2 = *(const float4*)(G + (size_t)s2 * OUT + lane * 4);
                float4 v3 = *(const float4*)(G + (size_t)s3 * OUT + lane * 4);
                float4 v4 = *(const float4*)(G + (size_t)s4 * OUT + lane * 4);
                float4 v5 = *(const float4*)(G + (size_t)s5 * OUT + lane * 4);
                float4 v6 = *(const float4*)(G + (size_t)s6 * OUT + lane * 4);
                float4 v7 = *(const float4*)(G + (size_t)s7 * OUT + lane * 4);
                accA[0] += v0.x; accA[1] += v0.y; accA[2] += v0.z; accA[3] += v0.w;
                accB[0] += v1.x; accB[1] += v1.y; accB[2] += v1.z; accB[3] += v1.w;
                accA[0] += v2.x; accA[1] += v2.y; accA[2] += v2.z; accA[3] += v2.w;
                accB[0] += v3.x; accB[1] += v3.y; accB[2] += v3.z; accB[3] += v3.w;
                accA[0] += v4.x; accA[1] += v4.y; accA[2] += v4.z; accA[3] += v4.w;
                accB[0] += v5.x; accB[1] += v5.y; accB[2] += v5.z; accB[3] += v5.w;
                accA[0] += v6.x; accA[1] += v6.y; accA[2] += v6.z; accA[3] += v6.w;
                accB[0] += v7.x; accB[1] += v7.y; accB[2] += v7.z; accB[3] += v7.w;
            } else {
                float2 v0 = *(const float2*)(G + (size_t)s0 * OUT + lane * 2);
                float2 v1 = *(const float2*)(G + (size_t)s1 * OUT + lane * 2);
                float2 v2 = *(const float2*)(G + (size_t)s2 * OUT + lane * 2);
                float2 v3 = *(const float2*)(G + (size_t)s3 * OUT + lane * 2);
                float2 v4 = *(const float2*)(G + (size_t)s4 * OUT + lane * 2);
                float2 v5 = *(const float2*)(G + (size_t)s5 * OUT + lane * 2);
                float2 v6 = *(const float2*)(G + (size_t)s6 * OUT + lane * 2);
                float2 v7 = *(const float2*)(G + (size_t)s7 * OUT + lane * 2);
                accA[0] += v0.x; accA[1] += v0.y;
                accB[0] += v1.x; accB[1] += v1.y;
                accA[0] += v2.x; accA[1] += v2.y;
                accB[0] += v3.x; accB[1] += v3.y;
                accA[0] += v4.x; accA[1] += v4.y;
                accB[0] += v5.x; accB[1] += v5.y;
                accA[0] += v6.x; accA[1] += v6.y;
                accB[0] += v7.x; accB[1] += v7.y;
            }
        }
        for (; j < cnt; j++) {
            int s = __shfl_sync(FULLMASK, my, j);
            if constexpr (VO == 4) {
                float4 v = *(const float4*)(G + (size_t)s * OUT + lane * 4);
                accA[0] += v.x; accA[1] += v.y; accA[2] += v.z; accA[3] += v.w;
            } else {
                float2 v = *(const float2*)(G + (size_t)s * OUT + lane * 2);
                accA[0] += v.x; accA[1] += v.y;
            }
        }
    }

    float dv = g_dinv[d];
    if constexpr (VO == 4) {
        float4 bv = *(const float4*)(bias + lane * 4);
        float4 o = make_float4((accA[0] + accB[0]) * dv + bv.x,
                               (accA[1] + accB[1]) * dv + bv.y,
                               (accA[2] + accB[2]) * dv + bv.z,
                               (accA[3] + accB[3]) * dv + bv.w);
        *(float4*)(out + (size_t)d * OUT + lane * 4) = o;
    } else {
        float2 bv = *(const float2*)(bias + lane * 2);
        float2 o = make_float2((accA[0] + accB[0]) * dv + bv.x,
                               (accA[1] + accB[1]) * dv + bv.y);
        *(float2*)(out + (size_t)d * OUT + lane * 2) = o;
    }
}

// ---------------------------------------------------------------------------
// Launch
// ---------------------------------------------------------------------------

extern "C" void kernel_launch(void* const* d_in, const int* in_sizes, int n_in,
                              void* d_out, int out_size) {
    const float* x  = (const float*)d_in[0];
    const int*   ei = (const int*)d_in[1];
    const float* W1 = (const float*)d_in[2];
    const float* b1 = (const float*)d_in[3];
    const float* W2 = (const float*)d_in[4];
    const float* b2 = (const float*)d_in[5];
    const float* W3 = (const float*)d_in[6];
    const float* b3 = (const float*)d_in[7];

    int E  = in_sizes[1] / 2;
    int D1 = in_sizes[3];            // 128
    int D0 = in_sizes[2] / D1;       // 128
    int N  = in_sizes[0] / D0;       // 100000
    if (N > MAXN) N = MAXN;
    if (E > MAXE) E = MAXE;

    const int* src = ei;
    const int* dst = ei + E;

    float *G, *H;
    cudaGetSymbolAddress((void**)&G, g_G);
    cudaGetSymbolAddress((void**)&H, g_H);
    void* degPtr;
    cudaGetSymbolAddress(&degPtr, g_deg);

    // dynamic smem sizes for GEMM variants
    const int SM128 = (128 * 128 + 8 * 8 * 128) * (int)sizeof(float);  // 96 KB
    const int SM64  = (128 * 64  + 8 * 8 * 128) * (int)sizeof(float);  // 64 KB
    cudaFuncSetAttribute(gemm_kernel<128, 128, false>,
                         cudaFuncAttributeMaxDynamicSharedMemorySize, SM128);
    cudaFuncSetAttribute(gemm_kernel<128, 128, true>,
                         cudaFuncAttributeMaxDynamicSharedMemorySize, SM128);
    cudaFuncSetAttribute(gemm_kernel<128, 64, true>,
                         cudaFuncAttributeMaxDynamicSharedMemorySize, SM64);

    int nb1024 = (N + 1023) / 1024;
    int ebs    = (E + 255) / 256;
    int gemmBlocks = (N + 63) / 64;
    int aggBlocks  = (N + 7) / 8;   // 8 warps/block, warp per node

    // ---- CSR build ----
    cudaMemsetAsync(degPtr, 0, (size_t)N * sizeof(int));
    count_deg_kernel<<<ebs, 256>>>(dst, E);
    scan1_kernel<<<nb1024, 1024>>>(N);   // also computes dinv
    scan2_kernel<<<1, 1024>>>(nb1024);
    scan3_kernel<<<nb1024, 1024>>>(N, E);
    scatter_kernel<<<ebs, 256>>>(src, dst, E);

    // ---- layer 1 ----
    gemm_kernel<128, 128, false><<<gemmBlocks, 256, SM128>>>(x, W1, G, N);
    agg_kernel<128><<<aggBlocks, 256>>>(G, b1, H, N);
    // ---- layer 2 (relu folded into GEMM input read) ----
    gemm_kernel<128, 128, true><<<gemmBlocks, 256, SM128>>>(H, W2, G, N);
    agg_kernel<128><<<aggBlocks, 256>>>(G, b2, H, N);
    // ---- layer 3 ----
    gemm_kernel<128, 64, true><<<gemmBlocks, 256, SM64>>>(H, W3, G, N);
    agg_kernel<64><<<aggBlocks, 256>>>(G, b3, (float*)d_out, N);
}